// round 2
// baseline (speedup 1.0000x reference)
#include <cuda_runtime.h>
#include <cuda_bf16.h>

// YOLOv1 loss, fused single kernel.
// B=16384, S=7 -> N = 802816 cells, 30 fp32 channels each for P and T.
// Each block: stage 128 rows of P,T to smem (coalesced float4), compute per-cell
// loss terms, block-reduce to a float4 partial. Last block to finish reduces all
// partials in fp64 and writes out[4] = {cls, conf, center+wh, total}.

#define NCELL (16384 * 7 * 7)   // 802816
#define BLK   128
#define NBLK  (NCELL / BLK)     // 6272 (exact)

__device__ float4 g_part[NBLK];
__device__ unsigned int g_count = 0;

__global__ __launch_bounds__(BLK) void yolo_fused(const float* __restrict__ P,
                                                  const float* __restrict__ T,
                                                  float* __restrict__ out)
{
    __shared__ float SP[BLK * 30];
    __shared__ float ST[BLK * 30];
    const int tid = threadIdx.x;

    // ---- coalesced float4 staging of this block's 128 rows ----
    const size_t base = (size_t)blockIdx.x * (BLK * 30);
    const float4* gp = (const float4*)(P + base);
    const float4* gt = (const float4*)(T + base);
    float4* sp4 = (float4*)SP;
    float4* st4 = (float4*)ST;
    const int NV4 = BLK * 30 / 4;   // 960
    #pragma unroll
    for (int i = 0; i < (NV4 + BLK - 1) / BLK; ++i) {
        int idx = tid + i * BLK;
        if (idx < NV4) { sp4[idx] = gp[idx]; st4[idx] = gt[idx]; }
    }
    __syncthreads();

    const float* p = SP + tid * 30;
    const float* t = ST + tid * 30;
    const float CELL = 1.0f / 7.0f;

    const float t0 = t[0], t1 = t[1], t2 = t[2], t3 = t[3], tc = t[4];

    // target corners — faithful to the reference's in-place bug:
    //   xy1 = xy*CELL - wh*0.5 ;  xy2 = xy1*CELL + wh*0.5
    const float twx = t2 * t2, twy = t3 * t3;
    const float tx1 = t0 * CELL - 0.5f * twx;
    const float ty1 = t1 * CELL - 0.5f * twy;
    const float tx2 = tx1 * CELL + 0.5f * twx;
    const float ty2 = ty1 * CELL + 0.5f * twy;
    const float area_t = (tx2 - tx1) * (ty2 - ty1);

    float iou0, iou1;
    #pragma unroll
    for (int b = 0; b < 2; ++b) {
        const float px = p[b * 5 + 0], py = p[b * 5 + 1];
        const float pw = p[b * 5 + 2], ph = p[b * 5 + 3];
        const float pwx = pw * pw, pwy = ph * ph;
        const float x1 = px * CELL - 0.5f * pwx;
        const float y1 = py * CELL - 0.5f * pwy;
        const float x2 = x1 * CELL + 0.5f * pwx;
        const float y2 = y1 * CELL + 0.5f * pwy;
        const float ltx = fmaxf(x1, tx1), lty = fmaxf(y1, ty1);
        const float rbx = fminf(x2, tx2), rby = fminf(y2, ty2);
        const float dx = fmaxf(rbx - ltx, 0.0f);
        const float dy = fmaxf(rby - lty, 0.0f);
        const float inter  = dx * dy;
        const float area_p = (x2 - x1) * (y2 - y1);
        const float v = inter / (area_p + area_t - inter);
        if (b == 0) iou0 = v; else iou1 = v;
    }
    // jnp.argmax: first max wins on ties -> strict '>' for index 1
    const int bi = (iou1 > iou0) ? 1 : 0;
    const int b5 = bi * 5;

    // class column: first max over t[10:30]
    int kcol = 10;
    float vb = t[10];
    #pragma unroll
    for (int k = 11; k < 30; ++k) {
        float v = t[k];
        if (v > vb) { vb = v; kcol = k; }
    }

    const bool obj = (tc == 1.0f);
    const bool noo = (tc == 0.0f);

    const float dk = p[kcol]   - t[kcol];
    const float dc = p[b5 + 4] - t[b5 + 4];
    const float d0 = p[b5 + 0] - t[b5 + 0];
    const float d1 = p[b5 + 1] - t[b5 + 1];
    const float d2 = p[b5 + 2] - t[b5 + 2];
    const float d3 = p[b5 + 3] - t[b5 + 3];
    const float d4 = p[4] - tc;
    const float d9 = p[9] - t[9];

    float4 acc;
    acc.x = obj ? dk * dk : 0.0f;                                   // cls
    acc.y = obj ? dc * dc : 0.0f;                                   // conf
    acc.z = obj ? (d0 * d0 + d1 * d1 + d2 * d2 + d3 * d3) : 0.0f;   // center+wh
    acc.w = noo ? (d4 * d4 + d9 * d9) : 0.0f;                       // noobj

    // ---- block reduce: warp shuffles then smem ----
    #pragma unroll
    for (int o = 16; o > 0; o >>= 1) {
        acc.x += __shfl_down_sync(0xffffffffu, acc.x, o);
        acc.y += __shfl_down_sync(0xffffffffu, acc.y, o);
        acc.z += __shfl_down_sync(0xffffffffu, acc.z, o);
        acc.w += __shfl_down_sync(0xffffffffu, acc.w, o);
    }
    __shared__ float4 wsum[BLK / 32];
    __shared__ bool s_last;
    if ((tid & 31) == 0) wsum[tid >> 5] = acc;
    __syncthreads();
    if (tid == 0) {
        float4 s = wsum[0];
        #pragma unroll
        for (int w = 1; w < BLK / 32; ++w) {
            s.x += wsum[w].x; s.y += wsum[w].y;
            s.z += wsum[w].z; s.w += wsum[w].w;
        }
        // bypass L1 so the last block sees it via L2
        __stcg(&g_part[blockIdx.x], s);
        __threadfence();
        unsigned int prev = atomicAdd(&g_count, 1u);
        s_last = (prev == (unsigned int)(NBLK - 1));
    }
    __syncthreads();
    if (!s_last) return;

    // ---- last block: fp64 reduction of all partials (L2-hot) ----
    double a0 = 0.0, a1 = 0.0, a2 = 0.0, a3 = 0.0;
    for (int i = tid; i < NBLK; i += BLK) {
        const float4 v = __ldcg(&g_part[i]);
        a0 += (double)v.x; a1 += (double)v.y;
        a2 += (double)v.z; a3 += (double)v.w;
    }
    __shared__ double s0[BLK], s1[BLK], s2[BLK], s3[BLK];
    s0[tid] = a0; s1[tid] = a1; s2[tid] = a2; s3[tid] = a3;
    __syncthreads();
    #pragma unroll
    for (int o = BLK / 2; o > 0; o >>= 1) {
        if (tid < o) {
            s0[tid] += s0[tid + o]; s1[tid] += s1[tid + o];
            s2[tid] += s2[tid + o]; s3[tid] += s3[tid + o];
        }
        __syncthreads();
    }
    if (tid == 0) {
        const float cls = (float)(5.0 * s0[0]);   // lambda_coord
        const float cnf = (float)(5.0 * s1[0]);
        const float cwh = (float)(5.0 * s2[0]);
        const float nob = (float)(0.5 * s3[0]);   // lambda_noobj
        out[0] = cls;
        out[1] = cnf;
        out[2] = cwh;
        out[3] = nob + cls + cnf + cwh;           // total
        g_count = 0;                              // reset for next graph replay
    }
}

extern "C" void kernel_launch(void* const* d_in, const int* in_sizes, int n_in,
                              void* d_out, int out_size)
{
    const float* P = (const float*)d_in[0];   // predictions [B,S,S,30] fp32
    const float* T = (const float*)d_in[1];   // targets     [B,S,S,30] fp32
    float* out = (float*)d_out;               // [cls, conf, center+wh, total]

    yolo_fused<<<NBLK, BLK>>>(P, T, out);
}

// round 3
// speedup vs baseline: 1.5351x; 1.5351x over previous
#include <cuda_runtime.h>
#include <cuda_bf16.h>

// YOLOv1 loss — persistent blocks, cp.async double-buffered staging, single launch.
// N = 802816 cells x 30 fp32 channels (P and T). 6272 tiles of 128 cells.

#define NCELL  (16384 * 7 * 7)       // 802816
#define TILE   128
#define NTILE  (NCELL / TILE)        // 6272
#define BLK    128
#define GRID   444                   // 3 blocks per SM on 148 SMs
#define TFL    (TILE * 30)           // floats per tile per tensor (3840)
#define TF4    (TFL / 4)             // float4 per tile per tensor (960)
#define SMEM_BYTES (2 * 2 * TFL * 4) // 2 stages x (P+T) x 15360 B = 61440

__device__ float4 g_part[GRID];
__device__ unsigned int g_count = 0;

__device__ __forceinline__ void cp16(float4* dst_smem, const float4* src_gmem) {
    unsigned int d = (unsigned int)__cvta_generic_to_shared(dst_smem);
    asm volatile("cp.async.cg.shared.global [%0], [%1], 16;\n" :: "r"(d), "l"(src_gmem));
}
__device__ __forceinline__ void cp_commit() {
    asm volatile("cp.async.commit_group;\n");
}
__device__ __forceinline__ void cp_wait1() {
    asm volatile("cp.async.wait_group 1;\n");
}

__device__ __forceinline__ void prefetch_tile(float* buf, int tile,
                                              const float* P, const float* T, int tid)
{
    const float4* gp = (const float4*)(P + (size_t)tile * TFL);
    const float4* gt = (const float4*)(T + (size_t)tile * TFL);
    float4* d = (float4*)buf;
    #pragma unroll
    for (int i = 0; i < (2 * TF4) / BLK; ++i) {      // 15 iterations
        int idx = tid + i * BLK;                      // 0..1919
        const float4* src = (idx < TF4) ? (gp + idx) : (gt + (idx - TF4));
        cp16(d + idx, src);
    }
}

__global__ __launch_bounds__(BLK) void yolo_fused(const float* __restrict__ P,
                                                  const float* __restrict__ T,
                                                  float* __restrict__ out)
{
    extern __shared__ float smem[];   // [stage][P(3840) | T(3840)]
    const int tid = threadIdx.x;
    const float CELL = 1.0f / 7.0f;

    float ax = 0.0f, ay = 0.0f, az = 0.0f, aw = 0.0f;

    int tile = blockIdx.x;
    int s = 0;
    prefetch_tile(smem, tile, P, T, tid);             // tile always valid (GRID < NTILE)
    cp_commit();

    for (; tile < NTILE; tile += GRID) {
        const int next = tile + GRID;
        if (next < NTILE) prefetch_tile(smem + (s ^ 1) * 2 * TFL, next, P, T, tid);
        cp_commit();
        cp_wait1();                                   // current tile's copy complete
        __syncthreads();

        const float* p = smem + s * 2 * TFL + tid * 30;
        const float* t = p + TFL;

        const float t0 = t[0], t1 = t[1], t2 = t[2], t3 = t[3], tc = t[4];

        // target corners — faithful to the reference's in-place bug:
        //   xy1 = xy*CELL - wh*0.5 ;  xy2 = xy1*CELL + wh*0.5
        const float twx = t2 * t2, twy = t3 * t3;
        const float tx1 = t0 * CELL - 0.5f * twx;
        const float ty1 = t1 * CELL - 0.5f * twy;
        const float tx2 = tx1 * CELL + 0.5f * twx;
        const float ty2 = ty1 * CELL + 0.5f * twy;
        const float area_t = (tx2 - tx1) * (ty2 - ty1);

        float iou0, iou1;
        #pragma unroll
        for (int b = 0; b < 2; ++b) {
            const float px = p[b * 5 + 0], py = p[b * 5 + 1];
            const float pw = p[b * 5 + 2], ph = p[b * 5 + 3];
            const float pwx = pw * pw, pwy = ph * ph;
            const float x1 = px * CELL - 0.5f * pwx;
            const float y1 = py * CELL - 0.5f * pwy;
            const float x2 = x1 * CELL + 0.5f * pwx;
            const float y2 = y1 * CELL + 0.5f * pwy;
            const float ltx = fmaxf(x1, tx1), lty = fmaxf(y1, ty1);
            const float rbx = fminf(x2, tx2), rby = fminf(y2, ty2);
            const float dx = fmaxf(rbx - ltx, 0.0f);
            const float dy = fmaxf(rby - lty, 0.0f);
            const float inter  = dx * dy;
            const float area_p = (x2 - x1) * (y2 - y1);
            const float v = inter / (area_p + area_t - inter);
            if (b == 0) iou0 = v; else iou1 = v;
        }
        const int b5 = (iou1 > iou0) ? 5 : 0;     // first max wins ties

        // class column: first max over t[10:30]
        int kcol = 10;
        float vb = t[10];
        #pragma unroll
        for (int k = 11; k < 30; ++k) {
            float v = t[k];
            if (v > vb) { vb = v; kcol = k; }
        }

        const bool obj = (tc == 1.0f);
        const bool noo = (tc == 0.0f);

        const float dk = p[kcol]   - t[kcol];
        const float dc = p[b5 + 4] - t[b5 + 4];
        const float d0 = p[b5 + 0] - t[b5 + 0];
        const float d1 = p[b5 + 1] - t[b5 + 1];
        const float d2 = p[b5 + 2] - t[b5 + 2];
        const float d3 = p[b5 + 3] - t[b5 + 3];
        const float d4 = p[4] - tc;
        const float d9 = p[9] - t[9];

        if (obj) {
            ax += dk * dk;                                   // cls
            ay += dc * dc;                                   // conf
            az += d0 * d0 + d1 * d1 + d2 * d2 + d3 * d3;     // center+wh
        }
        if (noo) aw += d4 * d4 + d9 * d9;                    // noobj

        __syncthreads();                                     // done reading buf[s]
        s ^= 1;
    }

    // ---- block reduce (once per block) ----
    #pragma unroll
    for (int o = 16; o > 0; o >>= 1) {
        ax += __shfl_down_sync(0xffffffffu, ax, o);
        ay += __shfl_down_sync(0xffffffffu, ay, o);
        az += __shfl_down_sync(0xffffffffu, az, o);
        aw += __shfl_down_sync(0xffffffffu, aw, o);
    }
    float4* wsum = (float4*)smem;      // staging buffers are dead now
    __shared__ bool s_last;
    if ((tid & 31) == 0) wsum[tid >> 5] = make_float4(ax, ay, az, aw);
    __syncthreads();
    if (tid == 0) {
        float4 sv = wsum[0];
        #pragma unroll
        for (int w = 1; w < BLK / 32; ++w) {
            sv.x += wsum[w].x; sv.y += wsum[w].y;
            sv.z += wsum[w].z; sv.w += wsum[w].w;
        }
        __stcg(&g_part[blockIdx.x], sv);
        __threadfence();
        unsigned int prev = atomicAdd(&g_count, 1u);
        s_last = (prev == (unsigned int)(GRID - 1));
    }
    __syncthreads();
    if (!s_last) return;

    // ---- last block: fp64 reduction of 444 partials ----
    double a0 = 0.0, a1 = 0.0, a2 = 0.0, a3 = 0.0;
    for (int i = tid; i < GRID; i += BLK) {
        const float4 v = __ldcg(&g_part[i]);
        a0 += (double)v.x; a1 += (double)v.y;
        a2 += (double)v.z; a3 += (double)v.w;
    }
    double* s0 = (double*)smem;        // reuse dynamic smem (4 x 128 doubles)
    double* s1 = s0 + BLK;
    double* s2 = s1 + BLK;
    double* s3 = s2 + BLK;
    __syncthreads();                   // wsum reads done before overwrite
    s0[tid] = a0; s1[tid] = a1; s2[tid] = a2; s3[tid] = a3;
    __syncthreads();
    #pragma unroll
    for (int o = BLK / 2; o > 0; o >>= 1) {
        if (tid < o) {
            s0[tid] += s0[tid + o]; s1[tid] += s1[tid + o];
            s2[tid] += s2[tid + o]; s3[tid] += s3[tid + o];
        }
        __syncthreads();
    }
    if (tid == 0) {
        const float cls = (float)(5.0 * s0[0]);   // lambda_coord
        const float cnf = (float)(5.0 * s1[0]);
        const float cwh = (float)(5.0 * s2[0]);
        const float nob = (float)(0.5 * s3[0]);   // lambda_noobj
        out[0] = cls;
        out[1] = cnf;
        out[2] = cwh;
        out[3] = nob + cls + cnf + cwh;           // total
        g_count = 0;                              // reset for next graph replay
    }
}

extern "C" void kernel_launch(void* const* d_in, const int* in_sizes, int n_in,
                              void* d_out, int out_size)
{
    const float* P = (const float*)d_in[0];   // predictions [B,S,S,30] fp32
    const float* T = (const float*)d_in[1];   // targets     [B,S,S,30] fp32
    float* out = (float*)d_out;               // [cls, conf, center+wh, total]

    cudaFuncSetAttribute(yolo_fused, cudaFuncAttributeMaxDynamicSharedMemorySize,
                         SMEM_BYTES);
    yolo_fused<<<GRID, BLK, SMEM_BYTES>>>(P, T, out);
}